// round 16
// baseline (speedup 1.0000x reference)
#include <cuda_runtime.h>

// DTM (distance-to-measure) on a 64x64 integer grid.
// Per (b,c) slice: bound = 0.05 * sum(w). Per point p: walk grid points in
// order of increasing squared distance, accumulate weight until crossing
// bound, output sqrt((sum_{d<d*} d^2 w + d*^2 (bound - cum_before)) / bound).
// Weights quantized to q = floor(w * 65535): we solve that perturbed problem
// (result is scale-invariant in w, so rel err ~1e-5 << 1e-3). Crossing index
// is computed EXACTLY in integers (one REDUX per 256 entries + int scans).
//
// Gather: weights in a guard-padded u16 array (pitch 127, rows -63..126,
// 63-entry front guard). idx = pbase2 + (off+8064) hits the real cell when
// in bounds and a provably-zero pad cell otherwise. No validity test.
//
// Table entry (u32): d2 << 14 | (dy*127+dx + 8064). Super-batch = 256
// entries; lane l owns entries {4l..4l+3} (seg0) and {128+4l..} (seg1).
//
// Each warp walks TWO points at once (groups g and 255-g, mirror-paired so
// crossing depths match): the table fetch is shared, the two gather/REDUX/
// scan chains are independent => 2x ILP under LDS/REDUX/shuffle latency.

#define HW 4096
#define NSLICE 12
#define NOFF 16129            // (dy,dx) in [-63,63]^2
#define NPAD 16384            // multiple of 256 (64 super-batches)
#define PITCH 127
#define GUARD 63
#define SMU16 24256           // 63 + 190*127 = 24193 used; rounded up
#define PADENT 16129u         // pad entry: d2=0, off lands in zero cells
#define GPB 48                // blocks per slice (group stride)

__device__ __align__(16) unsigned g_tab[NPAD];

// ---- build: 8 lanes per offset compute its sorted rank in closed form ----

__global__ void __launch_bounds__(256) k_build() {
    int gid = blockIdx.x * 256 + threadIdx.x;  // gid < 8*NPAD
    int i = gid >> 3;
    int q = gid & 7;
    int dy = i / 127 - 63;
    int dx = i % 127 - 63;
    int d2 = dy * dy + dx * dx;
    int pos = 0;
    if (i < NOFF) {
        for (int a = q; a <= 63; a += 8) {  // +-a handled together
            int na = d2 - a * a;
            if (na < 0) break;
            int s = (int)sqrtf((float)na);  // exact floor at these magnitudes
            bool perf = (s * s == na);
            if (na > 0) {                   // # of b with b^2 < na, |b|<=63
                int tt = perf ? s - 1 : s;
                if (tt > 63) tt = 63;
                int cb = 2 * tt + 1;
                pos += (a == 0) ? cb : 2 * cb;
            }
            if (perf && s <= 63) {          // ties b = +-s, lex (a,b) order
                if (a < dy) pos += (s == 0) ? 1 : 2;
                else if (a == dy) {
                    if (-s < dx) pos++;
                    if (s != 0 && s < dx) pos++;
                }
                if (a != 0) {
                    int aa = -a;
                    if (aa < dy) pos += (s == 0) ? 1 : 2;
                    else if (aa == dy) {
                        if (-s < dx) pos++;
                        if (s != 0 && s < dx) pos++;
                    }
                }
            }
        }
    }
    pos += __shfl_xor_sync(~0u, pos, 1);
    pos += __shfl_xor_sync(~0u, pos, 2);
    pos += __shfl_xor_sync(~0u, pos, 4);
    if (q == 0) {
        if (i >= NOFF) {
            g_tab[i] = PADENT;  // i < NPAD by grid sizing
        } else {
            g_tab[pos] = ((unsigned)d2 << 14) |
                         (unsigned)(dy * PITCH + dx + 8064);
        }
    }
}

// Resolve the crossing inside a 256-entry super-batch. Warp-uniform call.
// Returns this lane's value contribution for the batch up to the bound.
__device__ __forceinline__ float resolve_cross(
    uint4 c0, uint4 c1,
    int qA, int qB, int qC, int qD, int qE, int qF, int qG, int qH,
    int mi0, int mi1, int cum, int Bc, float boundf, int lane) {
    float add = 0.f;
    int s0 = mi0;
#pragma unroll
    for (int o = 1; o < 32; o <<= 1) {
        int u = __shfl_up_sync(~0u, s0, o);
        if (lane >= o) s0 += u;
    }
    int tot0 = __shfl_sync(~0u, s0, 31);
    uint4 cc;
    int b0, w0, w1, w2, w3;
    if (cum + tot0 >= Bc) {       // crossing in seg0
        cc = c0;
        b0 = cum + s0 - mi0;
        w0 = qA; w1 = qB; w2 = qC; w3 = qD;
    } else {                      // all of seg0, cross in seg1
        unsigned bs0 = (c0.x >> 14) * (unsigned)qA +
                       (c0.y >> 14) * (unsigned)qB +
                       (c0.z >> 14) * (unsigned)qC +
                       (c0.w >> 14) * (unsigned)qD;
        add += (float)bs0;
        int s1 = mi1;
#pragma unroll
        for (int o = 1; o < 32; o <<= 1) {
            int u = __shfl_up_sync(~0u, s1, o);
            if (lane >= o) s1 += u;
        }
        cc = c1;
        b0 = cum + tot0 + s1 - mi1;
        w0 = qE; w1 = qF; w2 = qG; w3 = qH;
    }
    int e1 = b0 + w0, e2 = e1 + w1, e3 = e2 + w2, e4 = e3 + w3;
    unsigned m = __ballot_sync(~0u, e4 >= Bc);  // bit31 guaranteed set
    int fl = __ffs(m) - 1;
    if (lane < fl) {
        unsigned bsl = (cc.x >> 14) * (unsigned)w0 +
                       (cc.y >> 14) * (unsigned)w1 +
                       (cc.z >> 14) * (unsigned)w2 +
                       (cc.w >> 14) * (unsigned)w3;
        add += (float)bsl;
    } else if (lane == fl) {
        float fA = (float)(int)(cc.x >> 14);
        float fB = (float)(int)(cc.y >> 14);
        float fC = (float)(int)(cc.z >> 14);
        float fD = (float)(int)(cc.w >> 14);
        if (e1 >= Bc) {
            add += fA * (boundf - (float)b0);
        } else {
            add += fA * (float)w0;
            if (e2 >= Bc) {
                add += fB * (boundf - (float)e1);
            } else {
                add += fB * (float)w1;
                if (e3 >= Bc) {
                    add += fC * (boundf - (float)e2);
                } else {
                    add += fC * (float)w2;
                    add += fD * (boundf - (float)e3);
                }
            }
        }
    }
    return add;
}

// ---- main: warp per point-PAIR, 256 entries per step ----

__global__ void __launch_bounds__(512, 3)
k_main(const float* __restrict__ x, float* __restrict__ out) {
    __shared__ unsigned short swq[SMU16];  // guard-padded quantized weights
    __shared__ int sredi[16];
    __shared__ int sS;

    int t = threadIdx.x;
    int slice = blockIdx.x / GPB;
    int r = blockIdx.x % GPB;      // this block's group residue
    const float4* src4 = (const float4*)(x + slice * HW);

    // zero everything (u32 writes), then place data
    unsigned* z32 = (unsigned*)swq;
    for (int i = t; i < SMU16 / 2; i += 512) z32[i] = 0;
    __syncthreads();

    // 8 contiguous cells per thread (never crosses a row)
    float4 v0 = src4[t * 2];
    float4 v1 = src4[t * 2 + 1];
    int cell = t * 8;
    int rb = GUARD + ((cell >> 6) + 63) * PITCH + (cell & 63);
    int q0 = (int)(v0.x * 65535.0f), q1 = (int)(v0.y * 65535.0f);
    int q2 = (int)(v0.z * 65535.0f), q3 = (int)(v0.w * 65535.0f);
    int q4 = (int)(v1.x * 65535.0f), q5 = (int)(v1.y * 65535.0f);
    int q6 = (int)(v1.z * 65535.0f), q7 = (int)(v1.w * 65535.0f);
    swq[rb + 0] = (unsigned short)q0; swq[rb + 1] = (unsigned short)q1;
    swq[rb + 2] = (unsigned short)q2; swq[rb + 3] = (unsigned short)q3;
    swq[rb + 4] = (unsigned short)q4; swq[rb + 5] = (unsigned short)q5;
    swq[rb + 6] = (unsigned short)q6; swq[rb + 7] = (unsigned short)q7;
    int ls = ((q0 + q1) + (q2 + q3)) + ((q4 + q5) + (q6 + q7));
#pragma unroll
    for (int o = 16; o; o >>= 1) ls += __shfl_xor_sync(~0u, ls, o);
    if ((t & 31) == 0) sredi[t >> 5] = ls;
    __syncthreads();
    if (t == 0) {
        int S = 0;
#pragma unroll
        for (int k = 0; k < 16; k++) S += sredi[k];
        sS = S;
    }
    __syncthreads();
    int S = sS;
    int Bc = (S + 19) / 20;            // first exact int cum >= Bc crosses
    float boundf = 0.05f * (float)S;   // value-space bound (q units)

    int w = t >> 5;
    int lane = t & 31;
    const uint4* tp = (const uint4*)g_tab;  // uint4 = 4 packed entries
    float* dst = out + slice * HW;

    // warp walks point pairs (g, 255-g); mirror pairing matches edge-ness
    for (int g = r; g < 128; g += GPB) {
        int gm = 255 - g;
        int p0 = (g << 4) + w;
        int p1 = (gm << 4) + w;
        int pb0 = GUARD + ((p0 >> 6) + 63) * PITCH + (p0 & 63) - 8064;
        int pb1 = GUARD + ((p1 >> 6) + 63) * PITCH + (p1 & 63) - 8064;

        int cum0 = 0, cum1 = 0;
        float accf0 = 0.f, accf1 = 0.f;
        bool done0 = false, done1 = false;  // warp-uniform

        for (int base = 0; base < NPAD; base += 256) {
            uint4 c0 = __ldg(tp + (base >> 2) + lane);       // shared fetch
            uint4 c1 = __ldg(tp + (base >> 2) + 32 + lane);

            if (!done0) {
                int qA = swq[pb0 + (int)(c0.x & 0x3FFFu)];
                int qB = swq[pb0 + (int)(c0.y & 0x3FFFu)];
                int qC = swq[pb0 + (int)(c0.z & 0x3FFFu)];
                int qD = swq[pb0 + (int)(c0.w & 0x3FFFu)];
                int qE = swq[pb0 + (int)(c1.x & 0x3FFFu)];
                int qF = swq[pb0 + (int)(c1.y & 0x3FFFu)];
                int qG = swq[pb0 + (int)(c1.z & 0x3FFFu)];
                int qH = swq[pb0 + (int)(c1.w & 0x3FFFu)];
                int mi0 = (qA + qB) + (qC + qD);
                int mi1 = (qE + qF) + (qG + qH);
                int tot = __reduce_add_sync(~0u, mi0 + mi1);
                if (cum0 + tot >= Bc) {
                    accf0 += resolve_cross(c0, c1, qA, qB, qC, qD, qE, qF,
                                           qG, qH, mi0, mi1, cum0, Bc,
                                           boundf, lane);
                    done0 = true;
                } else {
                    cum0 += tot;
                    unsigned bs0 = (c0.x >> 14) * (unsigned)qA +
                                   (c0.y >> 14) * (unsigned)qB +
                                   (c0.z >> 14) * (unsigned)qC +
                                   (c0.w >> 14) * (unsigned)qD;
                    unsigned bs1 = (c1.x >> 14) * (unsigned)qE +
                                   (c1.y >> 14) * (unsigned)qF +
                                   (c1.z >> 14) * (unsigned)qG +
                                   (c1.w >> 14) * (unsigned)qH;
                    accf0 += (float)bs0 + (float)bs1;
                }
            }
            if (!done1) {
                int qA = swq[pb1 + (int)(c0.x & 0x3FFFu)];
                int qB = swq[pb1 + (int)(c0.y & 0x3FFFu)];
                int qC = swq[pb1 + (int)(c0.z & 0x3FFFu)];
                int qD = swq[pb1 + (int)(c0.w & 0x3FFFu)];
                int qE = swq[pb1 + (int)(c1.x & 0x3FFFu)];
                int qF = swq[pb1 + (int)(c1.y & 0x3FFFu)];
                int qG = swq[pb1 + (int)(c1.z & 0x3FFFu)];
                int qH = swq[pb1 + (int)(c1.w & 0x3FFFu)];
                int mi0 = (qA + qB) + (qC + qD);
                int mi1 = (qE + qF) + (qG + qH);
                int tot = __reduce_add_sync(~0u, mi0 + mi1);
                if (cum1 + tot >= Bc) {
                    accf1 += resolve_cross(c0, c1, qA, qB, qC, qD, qE, qF,
                                           qG, qH, mi0, mi1, cum1, Bc,
                                           boundf, lane);
                    done1 = true;
                } else {
                    cum1 += tot;
                    unsigned bs0 = (c0.x >> 14) * (unsigned)qA +
                                   (c0.y >> 14) * (unsigned)qB +
                                   (c0.z >> 14) * (unsigned)qC +
                                   (c0.w >> 14) * (unsigned)qD;
                    unsigned bs1 = (c1.x >> 14) * (unsigned)qE +
                                   (c1.y >> 14) * (unsigned)qF +
                                   (c1.z >> 14) * (unsigned)qG +
                                   (c1.w >> 14) * (unsigned)qH;
                    accf1 += (float)bs0 + (float)bs1;
                }
            }
            if (done0 && done1) break;  // warp-uniform
        }

#pragma unroll
        for (int o = 16; o; o >>= 1) {
            accf0 += __shfl_xor_sync(~0u, accf0, o);
            accf1 += __shfl_xor_sync(~0u, accf1, o);
        }
        if (lane == 0) {
            dst[p0] = sqrtf(accf0 / boundf);
            dst[p1] = sqrtf(accf1 / boundf);
        }
    }
}

extern "C" void kernel_launch(void* const* d_in, const int* in_sizes, int n_in,
                              void* d_out, int out_size) {
    const float* x = (const float*)d_in[0];
    float* out = (float*)d_out;

    k_build<<<(NPAD * 8) / 256, 256>>>();
    k_main<<<NSLICE * GPB, 512>>>(x, out);
}